// round 11
// baseline (speedup 1.0000x reference)
#include <cuda_runtime.h>

#define HH 768
#define WW 768
#define CC 64
#define NSEG 385
#define NTHREADS 64
#define PER_T (HH / NTHREADS)     // 12 mask elems per scan thread
#define GRID_BLOCKS 4736          // 148 SM x 32 CTA slots
#define NWARPS_TOTAL (GRID_BLOCKS * 2)

// ---------------------------------------------------------------------------
// Fused grid pooling, WARP-per-(column-segment PAIR):
//   Each warp owns two horizontally adjacent cells (same row segment):
//   identical y bounds -> no divergence; contiguous x range [cs0, ce1) ->
//   one coalesced scan with predicated accumulator select (x < ce0).
//   Lane layout: cg = lane&15 (channel quad), xo = lane>>4 (x parity);
//   a warp access = 2 adjacent pixels = 512B contiguous.
//   Reduce = one shfl_xor(16) stage per cell, after ALL loads of both cells.
//   Traffic floor: 151MB read + 151MB write.
// ---------------------------------------------------------------------------
__global__ void __launch_bounds__(NTHREADS, 24)
fused_grid_pool(const float* __restrict__ in,
                const int* __restrict__ h_mask,
                const int* __restrict__ v_mask,
                float* __restrict__ out) {
    __shared__ int s_row_start[NSEG + 1];
    __shared__ int s_col_start[NSEG + 1];
    __shared__ int s_tmp[2];
    __shared__ int s_nrow, s_ncol;

    const int t = threadIdx.x;
    const int lane = t & 31, w = t >> 5;

    // ---- prolog: build segment starts for both masks ----
    #pragma unroll
    for (int axis = 0; axis < 2; ++axis) {
        const int* m = (axis == 0) ? h_mask : v_mask;
        int* start   = (axis == 0) ? s_row_start : s_col_start;

        const int base = t * PER_T;
        int pm = (base == 0) ? 1 : m[base - 1];   // pm=1 at i=0 forces rise[0]=0
        int rises = 0, cnt = 0;
        #pragma unroll
        for (int k = 0; k < PER_T; ++k) {
            const int mv = m[base + k];
            const int r = (mv == 1 && pm == 0);
            rises |= (r << k);
            cnt += r;
            pm = mv;
        }
        int v = cnt;
        #pragma unroll
        for (int o = 1; o < 32; o <<= 1) {
            int n = __shfl_up_sync(0xFFFFFFFFu, v, o);
            if (lane >= o) v += n;
        }
        if (lane == 31) s_tmp[w] = v;
        __syncthreads();
        const int add   = (w == 1) ? s_tmp[0] : 0;
        const int total = s_tmp[0] + s_tmp[1];
        const int excl  = v + add - cnt;

        int sid = excl;
        #pragma unroll
        for (int k = 0; k < PER_T; ++k) {
            if ((rises >> k) & 1) { ++sid; start[sid] = base + k; }
        }
        const int nseg = total + 1;
        if (t == 0) {
            start[0] = 0; start[nseg] = HH;
            if (axis == 0) s_nrow = nseg; else s_ncol = nseg;
        }
        __syncthreads();
    }

    const int nrow = s_nrow, ncol = s_ncol;
    const int npairs = (ncol + 1) >> 1;          // col-seg pairs per row seg
    const int total_units = nrow * npairs;

    const int cg = lane & 15;     // channel quad
    const int xo = lane >> 4;     // x parity
    const int gw = blockIdx.x * 2 + w;

    // ---- main: warp strides over (rseg, cseg-pair) units ----
    for (int unit = gw; unit < total_units; unit += NWARPS_TOTAL) {
        const int rseg = unit / npairs;
        const int pq   = unit - rseg * npairs;
        const int cseg0 = pq * 2;
        const bool has2 = (cseg0 + 1) < ncol;

        const int cs0 = s_col_start[cseg0];
        const int ce0 = s_col_start[cseg0 + 1];
        const int ce1 = has2 ? s_col_start[cseg0 + 2] : ce0;
        const int rs  = s_row_start[rseg], re = s_row_start[rseg + 1];

        float4 a0 = make_float4(0.f, 0.f, 0.f, 0.f);   // cell A, even y
        float4 a1 = make_float4(0.f, 0.f, 0.f, 0.f);   // cell A, odd y
        float4 b0 = make_float4(0.f, 0.f, 0.f, 0.f);   // cell B, even y
        float4 b1 = make_float4(0.f, 0.f, 0.f, 0.f);   // cell B, odd y

        int y = rs;
        for (; y + 1 < re; y += 2) {
            const float4* r0 = reinterpret_cast<const float4*>(
                in + (size_t)y * WW * CC);
            const float4* r1 = r0 + WW * (CC / 4);
            #pragma unroll 4
            for (int x = cs0 + xo; x < ce1; x += 2) {
                const float4 v0 = __ldg(&r0[x * 16 + cg]);
                const float4 v1 = __ldg(&r1[x * 16 + cg]);
                if (x < ce0) {
                    a0.x += v0.x; a0.y += v0.y; a0.z += v0.z; a0.w += v0.w;
                    a1.x += v1.x; a1.y += v1.y; a1.z += v1.z; a1.w += v1.w;
                } else {
                    b0.x += v0.x; b0.y += v0.y; b0.z += v0.z; b0.w += v0.w;
                    b1.x += v1.x; b1.y += v1.y; b1.z += v1.z; b1.w += v1.w;
                }
            }
        }
        if (y < re) {
            const float4* r0 = reinterpret_cast<const float4*>(
                in + (size_t)y * WW * CC);
            #pragma unroll 4
            for (int x = cs0 + xo; x < ce1; x += 2) {
                const float4 v0 = __ldg(&r0[x * 16 + cg]);
                if (x < ce0) {
                    a0.x += v0.x; a0.y += v0.y; a0.z += v0.z; a0.w += v0.w;
                } else {
                    b0.x += v0.x; b0.y += v0.y; b0.z += v0.z; b0.w += v0.w;
                }
            }
        }
        a0.x += a1.x; a0.y += a1.y; a0.z += a1.z; a0.w += a1.w;
        b0.x += b1.x; b0.y += b1.y; b0.z += b1.z; b0.w += b1.w;

        // reduce across x parities (lanes +-16), both cells
        a0.x += __shfl_xor_sync(0xFFFFFFFFu, a0.x, 16);
        a0.y += __shfl_xor_sync(0xFFFFFFFFu, a0.y, 16);
        a0.z += __shfl_xor_sync(0xFFFFFFFFu, a0.z, 16);
        a0.w += __shfl_xor_sync(0xFFFFFFFFu, a0.w, 16);
        b0.x += __shfl_xor_sync(0xFFFFFFFFu, b0.x, 16);
        b0.y += __shfl_xor_sync(0xFFFFFFFFu, b0.y, 16);
        b0.z += __shfl_xor_sync(0xFFFFFFFFu, b0.z, 16);
        b0.w += __shfl_xor_sync(0xFFFFFFFFu, b0.w, 16);

        const float h = (float)(re - rs);
        const float invA = 1.0f / (h * (float)(ce0 - cs0));
        const float invB = has2 ? 1.0f / (h * (float)(ce1 - ce0)) : 0.f;
        const float4 mvA = make_float4(a0.x * invA, a0.y * invA,
                                       a0.z * invA, a0.w * invA);
        const float4 mvB = make_float4(b0.x * invB, b0.y * invB,
                                       b0.z * invB, b0.w * invB);

        // broadcast: one contiguous sweep over both cells
        for (int y2 = rs; y2 < re; ++y2) {
            float4* ro = reinterpret_cast<float4*>(out + (size_t)y2 * WW * CC);
            #pragma unroll 4
            for (int x = cs0 + xo; x < ce1; x += 2)
                ro[x * 16 + cg] = (x < ce0) ? mvA : mvB;
        }
    }
}

// ---------------------------------------------------------------------------
extern "C" void kernel_launch(void* const* d_in, const int* in_sizes, int n_in,
                              void* d_out, int out_size) {
    const float* in = (const float*)d_in[0];
    const int*   hm = (const int*)d_in[1];
    const int*   vm = (const int*)d_in[2];
    float*       out = (float*)d_out;

    fused_grid_pool<<<GRID_BLOCKS, NTHREADS>>>(in, hm, vm, out);
}

// round 12
// speedup vs baseline: 1.1104x; 1.1104x over previous
#include <cuda_runtime.h>

#define HH 768
#define WW 768
#define CC 64
#define NSEG 385
#define NTHREADS 64
#define PER_T (HH / NTHREADS)     // 12 mask elems per scan thread
#define GRID_BLOCKS 4736          // 148 SM x 32 CTA slots
#define NWARPS_TOTAL (GRID_BLOCKS * 2)

// ---------------------------------------------------------------------------
// Fused grid pooling, WARP-per-cell (R8 layout, full-occupancy build):
//   prolog: every block redundantly scans both masks into SMEM segment tables.
//   main:   each warp owns one cell at a time. Lane layout: cg = lane&15
//           (channel quad), xo = lane>>4 (x parity). A warp access = 2
//           adjacent pixels = 512B fully coalesced. Reduce = ONE
//           shfl_xor(16). No barriers, no smem in the main loop.
//   regs budget = 32 -> 32 CTAs/SM -> 64/64 warps resident.
//   Traffic floor: 151MB read + 151MB write.
// ---------------------------------------------------------------------------
__global__ void __launch_bounds__(NTHREADS, 32)
fused_grid_pool(const float* __restrict__ in,
                const int* __restrict__ h_mask,
                const int* __restrict__ v_mask,
                float* __restrict__ out) {
    __shared__ int s_row_start[NSEG + 1];
    __shared__ int s_col_start[NSEG + 1];
    __shared__ int s_tmp[2];
    __shared__ int s_nrow, s_ncol;

    const int t = threadIdx.x;
    const int lane = t & 31, w = t >> 5;

    // ---- prolog: build segment starts for both masks ----
    #pragma unroll
    for (int axis = 0; axis < 2; ++axis) {
        const int* m = (axis == 0) ? h_mask : v_mask;
        int* start   = (axis == 0) ? s_row_start : s_col_start;

        const int base = t * PER_T;
        int pm = (base == 0) ? 1 : m[base - 1];   // pm=1 at i=0 forces rise[0]=0
        int rises = 0, cnt = 0;
        #pragma unroll
        for (int k = 0; k < PER_T; ++k) {
            const int mv = m[base + k];
            const int r = (mv == 1 && pm == 0);
            rises |= (r << k);
            cnt += r;
            pm = mv;
        }
        int v = cnt;
        #pragma unroll
        for (int o = 1; o < 32; o <<= 1) {
            int n = __shfl_up_sync(0xFFFFFFFFu, v, o);
            if (lane >= o) v += n;
        }
        if (lane == 31) s_tmp[w] = v;
        __syncthreads();
        const int add   = (w == 1) ? s_tmp[0] : 0;
        const int total = s_tmp[0] + s_tmp[1];
        const int excl  = v + add - cnt;

        int sid = excl;
        #pragma unroll
        for (int k = 0; k < PER_T; ++k) {
            if ((rises >> k) & 1) { ++sid; start[sid] = base + k; }
        }
        const int nseg = total + 1;
        if (t == 0) {
            start[0] = 0; start[nseg] = HH;
            if (axis == 0) s_nrow = nseg; else s_ncol = nseg;
        }
        __syncthreads();
    }

    const int nrow = s_nrow, ncol = s_ncol;
    const int total_cells = nrow * ncol;

    const int cg = lane & 15;     // channel quad
    const int xo = lane >> 4;     // x parity
    const int gw = blockIdx.x * 2 + w;

    // ---- main: warp-per-cell grid-stride, zero barriers ----
    for (int cell = gw; cell < total_cells; cell += NWARPS_TOTAL) {
        const int rseg = cell / ncol;
        const int cseg = cell - rseg * ncol;
        const int cs = s_col_start[cseg], ce = s_col_start[cseg + 1];
        const int rs = s_row_start[rseg], re = s_row_start[rseg + 1];

        float4 a0 = make_float4(0.f, 0.f, 0.f, 0.f);
        float4 a1 = make_float4(0.f, 0.f, 0.f, 0.f);

        int y = rs;
        for (; y + 1 < re; y += 2) {
            const float4* r0 = reinterpret_cast<const float4*>(
                in + (size_t)y * WW * CC);
            const float4* r1 = r0 + WW * (CC / 4);
            #pragma unroll 4
            for (int x = cs + xo; x < ce; x += 2) {
                const float4 v0 = __ldg(&r0[x * 16 + cg]);
                const float4 v1 = __ldg(&r1[x * 16 + cg]);
                a0.x += v0.x; a0.y += v0.y; a0.z += v0.z; a0.w += v0.w;
                a1.x += v1.x; a1.y += v1.y; a1.z += v1.z; a1.w += v1.w;
            }
        }
        if (y < re) {
            const float4* r0 = reinterpret_cast<const float4*>(
                in + (size_t)y * WW * CC);
            #pragma unroll 4
            for (int x = cs + xo; x < ce; x += 2) {
                const float4 v0 = __ldg(&r0[x * 16 + cg]);
                a0.x += v0.x; a0.y += v0.y; a0.z += v0.z; a0.w += v0.w;
            }
        }
        a0.x += a1.x; a0.y += a1.y; a0.z += a1.z; a0.w += a1.w;

        // single-stage reduce across the two x parities (lanes +-16)
        a0.x += __shfl_xor_sync(0xFFFFFFFFu, a0.x, 16);
        a0.y += __shfl_xor_sync(0xFFFFFFFFu, a0.y, 16);
        a0.z += __shfl_xor_sync(0xFFFFFFFFu, a0.z, 16);
        a0.w += __shfl_xor_sync(0xFFFFFFFFu, a0.w, 16);

        const float inv = 1.0f / (float)((re - rs) * (ce - cs));
        const float4 mv = make_float4(a0.x * inv, a0.y * inv,
                                      a0.z * inv, a0.w * inv);

        // broadcast: warp writes 2 whole pixels (512B) per sweep
        for (int y2 = rs; y2 < re; ++y2) {
            float4* ro = reinterpret_cast<float4*>(out + (size_t)y2 * WW * CC);
            #pragma unroll 4
            for (int x = cs + xo; x < ce; x += 2)
                ro[x * 16 + cg] = mv;
        }
    }
}

// ---------------------------------------------------------------------------
extern "C" void kernel_launch(void* const* d_in, const int* in_sizes, int n_in,
                              void* d_out, int out_size) {
    const float* in = (const float*)d_in[0];
    const int*   hm = (const int*)d_in[1];
    const int*   vm = (const int*)d_in[2];
    float*       out = (float*)d_out;

    fused_grid_pool<<<GRID_BLOCKS, NTHREADS>>>(in, hm, vm, out);
}